// round 6
// baseline (speedup 1.0000x reference)
#include <cuda_runtime.h>
#include <math.h>

// Problem dimensions (fixed by the dataset)
#define NN    32768      // total nodes B*NPG
#define BBg   8          // graphs
#define NPGc  4096       // nodes per graph
#define DINc  128
#define HHc   4
#define EEc   262144
#define CDIM  512        // H*DIN
#define BHc   32         // B*H

typedef unsigned long long ull;

__device__ __forceinline__ void fma2(ull &d, ull a, ull b) {
    asm("fma.rn.f32x2 %0, %1, %2, %0;" : "+l"(d) : "l"(a), "l"(b));
}
__device__ __forceinline__ float2 f2unpack(ull v) {
    float2 r;
    asm("mov.b64 {%0, %1}, %2;" : "=f"(r.x), "=f"(r.y) : "l"(v));
    return r;
}

// ---------------- scratch (device globals: allocation-free) ----------------
__device__ float g_q  [NN*CDIM];
__device__ float g_k  [NN*CDIM];
__device__ float g_cur[NN*CDIM];
__device__ float g_acc[NN*CDIM];
__device__ float g_gcn[NN*CDIM];
__device__ float g_kv  [BHc*DINc*DINc];
__device__ float g_vsum[BHc*DINc];
__device__ float g_ksum[BHc*DINc];
__device__ float g_den [NN*HHc];
__device__ int   g_deg   [NN];
__device__ float g_dis   [NN];
__device__ int   g_cursor[NN];
__device__ int   g_rowptr[NN];
__device__ int   g_incl  [NN];
__device__ int   g_bsum[128];
__device__ int   g_boff[128];
__device__ int   g_ecol[EEc];
__device__ float g_ew  [EEc];

// ---------------- init: cur = acc = broadcast(x over heads) ----------------
__global__ void k_init(const float* __restrict__ x) {
    int i = blockIdx.x * blockDim.x + threadIdx.x;     // float4 index over NN*CDIM/4
    int n  = i >> 7;            // 128 float4 per node
    int r  = i & 127;
    int d4 = r & 31;            // float4 within the 128-dim feature (head-replicated)
    float4 v = reinterpret_cast<const float4*>(x)[n * 32 + d4];
    reinterpret_cast<float4*>(g_cur)[i] = v;
    reinterpret_cast<float4*>(g_acc)[i] = v;
}

__global__ void k_zero_pre() {
    int i = blockIdx.x * blockDim.x + threadIdx.x;
    if (i < NN) { g_deg[i] = 0; g_cursor[i] = 0; }
    if (i < BHc * DINc) g_ksum[i] = 0.f;
}

__global__ void k_count(const int* __restrict__ row) {
    int e = blockIdx.x * blockDim.x + threadIdx.x;
    if (e < EEc) atomicAdd(&g_deg[row[e]], 1);
}

__global__ void k_dis() {
    int n = blockIdx.x * blockDim.x + threadIdx.x;
    if (n < NN) {
        int d = g_deg[n];
        g_dis[n] = (d > 0) ? (1.0f / sqrtf((float)d)) : 0.0f;
    }
}

// ---------------- prefix scan over deg -> rowptr (exclusive) ----------------
__global__ void k_scanA() {
    __shared__ int s[256];
    int t = threadIdx.x;
    int i = blockIdx.x * 256 + t;
    int v = g_deg[i];
    s[t] = v; __syncthreads();
    for (int off = 1; off < 256; off <<= 1) {
        int u = (t >= off) ? s[t - off] : 0;
        __syncthreads();
        s[t] += u;
        __syncthreads();
    }
    g_incl[i] = s[t];
    if (t == 255) g_bsum[blockIdx.x] = s[255];
}

__global__ void k_scanB() {
    __shared__ int s[128];
    int t = threadIdx.x;
    int v = g_bsum[t];
    s[t] = v; __syncthreads();
    for (int off = 1; off < 128; off <<= 1) {
        int u = (t >= off) ? s[t - off] : 0;
        __syncthreads();
        s[t] += u;
        __syncthreads();
    }
    g_boff[t] = s[t] - v;     // exclusive block offset
}

__global__ void k_scanC() {
    int i = blockIdx.x * blockDim.x + threadIdx.x;
    if (i < NN) g_rowptr[i] = g_incl[i] - g_deg[i] + g_boff[i >> 8];
}

__global__ void k_fill(const int* __restrict__ row, const int* __restrict__ col) {
    int e = blockIdx.x * blockDim.x + threadIdx.x;
    if (e < EEc) {
        int r = row[e], c = col[e];
        int pos = g_rowptr[r] + atomicAdd(&g_cursor[r], 1);
        g_ecol[pos] = c;
        g_ew[pos]   = g_dis[r] * g_dis[c];
    }
}

// ---------------- SGEMM via FFMA2 k-pairs: C[M,N] = scale*(A[M,K]@B[N,K]^T + bias[N])
// Tile 128m x 64n, 128 threads, 8x8 per thread, K-chunk 32.
// Shared layout [row][k] stride 34 (k-contiguous pairs for fma.rn.f32x2).
__global__ void __launch_bounds__(128)
k_gemm(const float* __restrict__ A, const float* __restrict__ B,
       const float* __restrict__ bias, float* __restrict__ C,
       int M, int N, int K, float scale) {
    __shared__ __align__(16) float sA[128 * 34];
    __shared__ __align__(16) float sB[64 * 34];
    int t  = threadIdx.x;
    int bm = blockIdx.y * 128;
    int bn = blockIdx.x * 64;
    int m0 = (t >> 3) * 8;     // 16 groups x 8 rows
    int n0 = t & 7;            // col = bn + n0 + 8*j

    ull acc[8][8];
    #pragma unroll
    for (int i = 0; i < 8; i++)
        #pragma unroll
        for (int j = 0; j < 8; j++) acc[i][j] = 0ull;

    for (int kc = 0; kc < K; kc += 32) {
        // load A tile 128x32 (8 float4/thread) and B tile 64x32 (4/thread)
        #pragma unroll
        for (int l = 0; l < 8; l++) {
            int id = t + 128 * l;
            int row = id >> 3;
            int c4  = (id & 7) * 4;
            float4 v = *reinterpret_cast<const float4*>(&A[(bm + row) * K + kc + c4]);
            *reinterpret_cast<float2*>(&sA[row * 34 + c4])     = make_float2(v.x, v.y);
            *reinterpret_cast<float2*>(&sA[row * 34 + c4 + 2]) = make_float2(v.z, v.w);
        }
        #pragma unroll
        for (int l = 0; l < 4; l++) {
            int id = t + 128 * l;
            int row = id >> 3;
            int c4  = (id & 7) * 4;
            float4 v = *reinterpret_cast<const float4*>(&B[(bn + row) * K + kc + c4]);
            *reinterpret_cast<float2*>(&sB[row * 34 + c4])     = make_float2(v.x, v.y);
            *reinterpret_cast<float2*>(&sB[row * 34 + c4 + 2]) = make_float2(v.z, v.w);
        }
        __syncthreads();
        #pragma unroll 4
        for (int kk = 0; kk < 32; kk += 2) {
            ull a[8], b[8];
            #pragma unroll
            for (int i = 0; i < 8; i++)
                a[i] = *reinterpret_cast<const ull*>(&sA[(m0 + i) * 34 + kk]);
            #pragma unroll
            for (int j = 0; j < 8; j++)
                b[j] = *reinterpret_cast<const ull*>(&sB[(n0 + 8 * j) * 34 + kk]);
            #pragma unroll
            for (int i = 0; i < 8; i++)
                #pragma unroll
                for (int j = 0; j < 8; j++) fma2(acc[i][j], a[i], b[j]);
        }
        __syncthreads();
    }

    float bb[8];
    #pragma unroll
    for (int j = 0; j < 8; j++) bb[j] = bias[bn + n0 + 8 * j];
    #pragma unroll
    for (int i = 0; i < 8; i++) {
        int gm = bm + m0 + i;
        #pragma unroll
        for (int j = 0; j < 8; j++) {
            float2 p = f2unpack(acc[i][j]);
            C[gm * N + bn + n0 + 8 * j] = scale * (p.x + p.y + bb[j]);
        }
    }
}

// ---------------- L2-normalize rows of 128 (one warp per (n,h)) ----------------
__global__ void k_norm(float* __restrict__ buf) {
    int gt   = blockIdx.x * blockDim.x + threadIdx.x;
    int w    = gt >> 5;                 // warp over NN*HH rows
    int lane = threadIdx.x & 31;
    float4 v = reinterpret_cast<float4*>(buf)[w * 32 + lane];
    float ss = v.x * v.x + v.y * v.y + v.z * v.z + v.w * v.w;
    #pragma unroll
    for (int off = 16; off > 0; off >>= 1) ss += __shfl_xor_sync(0xffffffffu, ss, off);
    float r = 1.0f / sqrtf(ss);
    v.x *= r; v.y *= r; v.z *= r; v.w *= r;
    reinterpret_cast<float4*>(buf)[w * 32 + lane] = v;
}

// ---------------- column sums over nodes per (b,h): which==0 -> ksum from g_k, 1 -> vsum from g_cur
__global__ void k_colsum(int which) {
    int bh = blockIdx.x;
    int b = bh >> 2, h = bh & 3;
    int nb = blockIdx.y * 128;
    int e = threadIdx.x;
    const float* src = which ? g_cur : g_k;
    float* dst       = which ? g_vsum : g_ksum;
    float s = 0.f;
    for (int n = 0; n < 128; n++)
        s += src[((b * NPGc + nb + n) * HHc + h) * DINc + e];
    atomicAdd(&dst[bh * DINc + e], s);
}

// ---------------- den[n,h] = q . ksum + n_nodes (iteration-invariant) ----------------
__global__ void k_den(const int* __restrict__ n_nodes) {
    int gt   = blockIdx.x * blockDim.x + threadIdx.x;
    int w    = gt >> 5;                 // (n,h) index
    int lane = threadIdx.x & 31;
    int n = w >> 2, h = w & 3;
    int b = n >> 12;                    // NPG = 4096
    float4 q = reinterpret_cast<float4*>(g_q)[w * 32 + lane];
    float4 s = reinterpret_cast<float4*>(g_ksum)[((b << 2) | h) * 32 + lane];
    float d = q.x * s.x + q.y * s.y + q.z * s.z + q.w * s.w;
    #pragma unroll
    for (int off = 16; off > 0; off >>= 1) d += __shfl_xor_sync(0xffffffffu, d, off);
    if (lane == 0) g_den[w] = d + (float)n_nodes[b];
}

__global__ void k_zero_iter() {
    int i = blockIdx.x * blockDim.x + threadIdx.x;
    if (i < BHc * DINc * DINc) g_kv[i] = 0.f;
    if (i < BHc * DINc) g_vsum[i] = 0.f;
}

// ---------------- kv[b,h] = sum_n k[n] (outer) v[n] : FFMA2 node-pairs ----------------
// Shared layouts transposed: sK[d][node], sV[e][node] (node contiguous), stride 34.
__global__ void __launch_bounds__(256) k_kv() {
    __shared__ __align__(16) float sK[128 * 34];
    __shared__ __align__(16) float sV[128 * 34];
    int bh = blockIdx.x, sp = blockIdx.y;
    int b = bh >> 2, h = bh & 3;
    int t = threadIdx.x;
    int m0 = (t >> 4) * 8;     // d-dim group
    int e0 = t & 15;           // e = e0 + 16*j
    int nbase = sp * 512;

    ull acc[8][8];
    #pragma unroll
    for (int i = 0; i < 8; i++)
        #pragma unroll
        for (int j = 0; j < 8; j++) acc[i][j] = 0ull;

    for (int st = 0; st < 512; st += 32) {
        // load 32 nodes x 128 dims of K and V, transposed scatter into shared
        #pragma unroll
        for (int l = 0; l < 4; l++) {
            int id = t + 256 * l;          // 0..1023
            int d4 = id & 31;              // coalesced along dim
            int nl = id >> 5;              // node 0..31
            int fidx = ((b * NPGc + nbase + st + nl) * HHc + h) * DINc + d4 * 4;
            float4 vk = *reinterpret_cast<const float4*>(&g_k[fidx]);
            sK[(4 * d4 + 0) * 34 + nl] = vk.x;
            sK[(4 * d4 + 1) * 34 + nl] = vk.y;
            sK[(4 * d4 + 2) * 34 + nl] = vk.z;
            sK[(4 * d4 + 3) * 34 + nl] = vk.w;
            float4 vv = *reinterpret_cast<const float4*>(&g_cur[fidx]);
            sV[(4 * d4 + 0) * 34 + nl] = vv.x;
            sV[(4 * d4 + 1) * 34 + nl] = vv.y;
            sV[(4 * d4 + 2) * 34 + nl] = vv.z;
            sV[(4 * d4 + 3) * 34 + nl] = vv.w;
        }
        __syncthreads();
        #pragma unroll 4
        for (int kk = 0; kk < 32; kk += 2) {
            ull a[8], v[8];
            #pragma unroll
            for (int i = 0; i < 8; i++)
                a[i] = *reinterpret_cast<const ull*>(&sK[(m0 + i) * 34 + kk]);
            #pragma unroll
            for (int j = 0; j < 8; j++)
                v[j] = *reinterpret_cast<const ull*>(&sV[(e0 + 16 * j) * 34 + kk]);
            #pragma unroll
            for (int i = 0; i < 8; i++)
                #pragma unroll
                for (int j = 0; j < 8; j++) fma2(acc[i][j], a[i], v[j]);
        }
        __syncthreads();
    }
    float* dst = &g_kv[bh * DINc * DINc];
    #pragma unroll
    for (int i = 0; i < 8; i++)
        #pragma unroll
        for (int j = 0; j < 8; j++) {
            float2 p = f2unpack(acc[i][j]);
            atomicAdd(&dst[(m0 + i) * 128 + e0 + 16 * j], p.x + p.y);
        }
}

// ---------------- GCN gather: gcn[n] = sum_{e in CSR row n} w[e] * cur[col[e]] ----------------
__global__ void k_gcn() {
    int n = blockIdx.x;
    int t = threadIdx.x;             // 0..127, one float4 of the 512-wide feature
    int s = g_rowptr[n];
    int e = s + g_deg[n];
    float4 acc = make_float4(0.f, 0.f, 0.f, 0.f);
    for (int i = s; i < e; i++) {
        int   c = g_ecol[i];
        float w = g_ew[i];
        float4 v = reinterpret_cast<const float4*>(g_cur)[c * 128 + t];
        acc.x += w * v.x; acc.y += w * v.y; acc.z += w * v.z; acc.w += w * v.w;
    }
    reinterpret_cast<float4*>(g_gcn)[n * 128 + t] = acc;
}

// ---------------- combine: attn = (q@kv + vsum)/den; cur = .5*gcn + .5*attn; acc += cur
// Tile: 64 nodes x 128 e per block, 128 threads, 8x8/thread, d chunked by 32, FFMA2 d-pairs.
__global__ void __launch_bounds__(128) k_combine() {
    __shared__ __align__(16) float sQ  [64 * 34];    // [node][d]
    __shared__ __align__(16) float sKVt[128 * 34];   // [e][d]
    int bh = blockIdx.x, ch = blockIdx.y;
    int b = bh >> 2, h = bh & 3;
    int t = threadIdx.x;
    int nbase = ch * 64;
    int m0 = (t >> 4) * 8;     // node group (8 groups x 8 = 64)
    int e0 = t & 15;           // e = e0 + 16*j

    ull acc[8][8];
    #pragma unroll
    for (int i = 0; i < 8; i++)
        #pragma unroll
        for (int j = 0; j < 8; j++) acc[i][j] = 0ull;

    for (int kc = 0; kc < 128; kc += 32) {
        // sQ: 64 nodes x 32 dims (4 float4/thread)
        #pragma unroll
        for (int l = 0; l < 4; l++) {
            int id = t + 128 * l;
            int row = id >> 3;            // node 0..63
            int c4  = (id & 7) * 4;
            int fidx = ((b * NPGc + nbase + row) * HHc + h) * DINc + kc + c4;
            float4 v = *reinterpret_cast<const float4*>(&g_q[fidx]);
            *reinterpret_cast<float2*>(&sQ[row * 34 + c4])     = make_float2(v.x, v.y);
            *reinterpret_cast<float2*>(&sQ[row * 34 + c4 + 2]) = make_float2(v.z, v.w);
        }
        // sKVt: transpose of kv[kc..kc+31][0..127] (8 float4/thread scatter)
        #pragma unroll
        for (int l = 0; l < 8; l++) {
            int id = t + 128 * l;          // 0..1023
            int e4 = id & 31;
            int dl = id >> 5;              // 0..31
            float4 v = *reinterpret_cast<const float4*>(
                &g_kv[bh * DINc * DINc + (kc + dl) * 128 + 4 * e4]);
            sKVt[(4 * e4 + 0) * 34 + dl] = v.x;
            sKVt[(4 * e4 + 1) * 34 + dl] = v.y;
            sKVt[(4 * e4 + 2) * 34 + dl] = v.z;
            sKVt[(4 * e4 + 3) * 34 + dl] = v.w;
        }
        __syncthreads();
        #pragma unroll 4
        for (int kk = 0; kk < 32; kk += 2) {
            ull a[8], kvp[8];
            #pragma unroll
            for (int i = 0; i < 8; i++)
                a[i] = *reinterpret_cast<const ull*>(&sQ[(m0 + i) * 34 + kk]);
            #pragma unroll
            for (int j = 0; j < 8; j++)
                kvp[j] = *reinterpret_cast<const ull*>(&sKVt[(e0 + 16 * j) * 34 + kk]);
            #pragma unroll
            for (int i = 0; i < 8; i++)
                #pragma unroll
                for (int j = 0; j < 8; j++) fma2(acc[i][j], a[i], kvp[j]);
        }
        __syncthreads();
    }

    float vs[8];
    #pragma unroll
    for (int j = 0; j < 8; j++) vs[j] = g_vsum[bh * DINc + e0 + 16 * j];

    #pragma unroll
    for (int i = 0; i < 8; i++) {
        int gn = b * NPGc + nbase + m0 + i;
        float inv = 1.0f / g_den[gn * HHc + h];
        int base = (gn * HHc + h) * DINc;
        #pragma unroll
        for (int j = 0; j < 8; j++) {
            int e = e0 + 16 * j;
            float2 p = f2unpack(acc[i][j]);
            float attn = (p.x + p.y + vs[j]) * inv;
            float o = 0.5f * (g_gcn[base + e] + attn);
            g_cur[base + e] = o;
            g_acc[base + e] += o;
        }
    }
}

// ---------------- launcher ----------------
extern "C" void kernel_launch(void* const* d_in, const int* in_sizes, int n_in,
                              void* d_out, int out_size) {
    const float* x    = (const float*)d_in[0];
    const float* Wq_w = (const float*)d_in[1];
    const float* Wq_b = (const float*)d_in[2];
    const float* Wk_w = (const float*)d_in[3];
    const float* Wk_b = (const float*)d_in[4];
    const float* Wo_w = (const float*)d_in[5];
    const float* Wo_b = (const float*)d_in[6];
    const int*   edge = (const int*)d_in[7];
    const int*   nnod = (const int*)d_in[8];
    const int* row = edge;
    const int* col = edge + EEc;
    float* out = (float*)d_out;

    float *pq, *pk, *pacc;
    cudaGetSymbolAddress((void**)&pq,   g_q);
    cudaGetSymbolAddress((void**)&pk,   g_k);
    cudaGetSymbolAddress((void**)&pacc, g_acc);

    // init + graph preprocessing (once per call)
    k_init<<<16384, 256>>>(x);
    k_zero_pre<<<128, 256>>>();
    k_count<<<1024, 256>>>(row);
    k_dis<<<128, 256>>>();
    k_scanA<<<128, 256>>>();
    k_scanB<<<1, 128>>>();
    k_scanC<<<128, 256>>>();
    k_fill<<<1024, 256>>>(row, col);

    // projections + normalization + invariant attention terms
    k_gemm<<<dim3(8, 256), 128>>>(x, Wq_w, Wq_b, pq, NN, CDIM, DINc, 1.0f);
    k_gemm<<<dim3(8, 256), 128>>>(x, Wk_w, Wk_b, pk, NN, CDIM, DINc, 1.0f);
    k_norm<<<16384, 256>>>(pq);
    k_norm<<<16384, 256>>>(pk);
    k_colsum<<<dim3(32, 32), 128>>>(0);     // ksum
    k_den<<<16384, 256>>>(nnod);

    // K_ORDER = 4 propagation steps
    for (int it = 0; it < 4; it++) {
        k_zero_iter<<<2048, 256>>>();
        k_colsum<<<dim3(32, 32), 128>>>(1); // vsum from cur
        k_kv<<<dim3(32, 8), 256>>>();
        k_gcn<<<32768, 128>>>();
        k_combine<<<dim3(32, 64), 128>>>();
    }

    // out = (acc @ Wo^T + b) / H
    k_gemm<<<dim3(2, 256), 128>>>(pacc, Wo_w, Wo_b, out, NN, DINc, CDIM, 0.25f);
}

// round 7
// speedup vs baseline: 2.7239x; 2.7239x over previous
#include <cuda_runtime.h>
#include <math.h>

// Problem dimensions (fixed by the dataset)
#define NN    32768      // total nodes B*NPG
#define BBg   8          // graphs
#define NPGc  4096       // nodes per graph
#define DINc  128
#define HHc   4
#define EEc   262144
#define CDIM  512        // H*DIN
#define BHc   32         // B*H

// ---------------- tf32 helpers ----------------
__device__ __forceinline__ float tf32r(float x) {
    unsigned r;
    asm("cvt.rna.tf32.f32 %0, %1;" : "=r"(r) : "f"(x));
    return __uint_as_float(r);
}
__device__ __forceinline__ void mma8(float* c, const unsigned* a, const unsigned* b) {
    asm volatile(
        "mma.sync.aligned.m16n8k8.row.col.f32.tf32.tf32.f32 "
        "{%0,%1,%2,%3},{%4,%5,%6,%7},{%8,%9},{%0,%1,%2,%3};\n"
        : "+f"(c[0]), "+f"(c[1]), "+f"(c[2]), "+f"(c[3])
        : "r"(a[0]), "r"(a[1]), "r"(a[2]), "r"(a[3]), "r"(b[0]), "r"(b[1]));
}
__device__ __forceinline__ unsigned fbits(float x) { return __float_as_uint(x); }

// ---------------- scratch (device globals: allocation-free) ----------------
__device__ float g_q  [NN*CDIM];
__device__ float g_k  [NN*CDIM];
__device__ float g_cur[NN*CDIM];
__device__ float g_acc[NN*CDIM];
__device__ float g_gcn[NN*CDIM];
__device__ float g_kT  [BHc*DINc*NPGc];   // [bh][d][n]
__device__ float g_curT[BHc*DINc*NPGc];   // [bh][e][n]
__device__ float g_kvp [8*BHc*DINc*DINc]; // per-split partials
__device__ float g_kv  [BHc*DINc*DINc];
__device__ float g_vsum[BHc*DINc];
__device__ float g_ksum[BHc*DINc];
__device__ float g_den [NN*HHc];
__device__ int   g_deg   [NN];
__device__ float g_dis   [NN];
__device__ int   g_cursor[NN];
__device__ int   g_rowptr[NN];
__device__ int   g_incl  [NN];
__device__ int   g_bsum[128];
__device__ int   g_boff[128];
__device__ int   g_ecol[EEc];
__device__ float g_ew  [EEc];

// ---------------- init: cur = acc = broadcast(x over heads) ----------------
__global__ void k_init(const float* __restrict__ x) {
    int i = blockIdx.x * blockDim.x + threadIdx.x;     // float4 index over NN*CDIM/4
    int n  = i >> 7;            // 128 float4 per node
    int r  = i & 127;
    int d4 = r & 31;            // float4 within the 128-dim feature (head-replicated)
    float4 v = reinterpret_cast<const float4*>(x)[n * 32 + d4];
    reinterpret_cast<float4*>(g_cur)[i] = v;
    reinterpret_cast<float4*>(g_acc)[i] = v;
}

__global__ void k_zero_pre() {
    int i = blockIdx.x * blockDim.x + threadIdx.x;
    if (i < NN) { g_deg[i] = 0; g_cursor[i] = 0; }
    if (i < BHc * DINc) g_ksum[i] = 0.f;
}

__global__ void k_count(const int* __restrict__ row) {
    int e = blockIdx.x * blockDim.x + threadIdx.x;
    if (e < EEc) atomicAdd(&g_deg[row[e]], 1);
}

__global__ void k_dis() {
    int n = blockIdx.x * blockDim.x + threadIdx.x;
    if (n < NN) {
        int d = g_deg[n];
        g_dis[n] = (d > 0) ? (1.0f / sqrtf((float)d)) : 0.0f;
    }
}

// ---------------- prefix scan over deg -> rowptr (exclusive) ----------------
__global__ void k_scanA() {
    __shared__ int s[256];
    int t = threadIdx.x;
    int i = blockIdx.x * 256 + t;
    int v = g_deg[i];
    s[t] = v; __syncthreads();
    for (int off = 1; off < 256; off <<= 1) {
        int u = (t >= off) ? s[t - off] : 0;
        __syncthreads();
        s[t] += u;
        __syncthreads();
    }
    g_incl[i] = s[t];
    if (t == 255) g_bsum[blockIdx.x] = s[255];
}

__global__ void k_scanB() {
    __shared__ int s[128];
    int t = threadIdx.x;
    int v = g_bsum[t];
    s[t] = v; __syncthreads();
    for (int off = 1; off < 128; off <<= 1) {
        int u = (t >= off) ? s[t - off] : 0;
        __syncthreads();
        s[t] += u;
        __syncthreads();
    }
    g_boff[t] = s[t] - v;     // exclusive block offset
}

__global__ void k_scanC() {
    int i = blockIdx.x * blockDim.x + threadIdx.x;
    if (i < NN) g_rowptr[i] = g_incl[i] - g_deg[i] + g_boff[i >> 8];
}

__global__ void k_fill(const int* __restrict__ row, const int* __restrict__ col) {
    int e = blockIdx.x * blockDim.x + threadIdx.x;
    if (e < EEc) {
        int r = row[e], c = col[e];
        int pos = g_rowptr[r] + atomicAdd(&g_cursor[r], 1);
        g_ecol[pos] = c;
        g_ew[pos]   = g_dis[r] * g_dis[c];
    }
}

// ---------------- tiled transpose: dst[bh][d][n] = src[((b*NPG+n)*H+h)*DIN + d] -----
__global__ void k_transpose(const float* __restrict__ src, float* __restrict__ dst) {
    __shared__ float s[32 * 33];
    int bh = blockIdx.x;
    int b = bh >> 2, h = bh & 3;
    int n0 = blockIdx.y * 32, d0 = blockIdx.z * 32;
    int t = threadIdx.x;
    {
        int nl = t >> 3, d4 = (t & 7) * 4;
        float4 v = *reinterpret_cast<const float4*>(
            &src[((b * NPGc + n0 + nl) * HHc + h) * DINc + d0 + d4]);
        s[(d4 + 0) * 33 + nl] = v.x;
        s[(d4 + 1) * 33 + nl] = v.y;
        s[(d4 + 2) * 33 + nl] = v.z;
        s[(d4 + 3) * 33 + nl] = v.w;
    }
    __syncthreads();
    {
        int dl = t >> 3, n4 = (t & 7) * 4;
        float4 v;
        v.x = s[dl * 33 + n4 + 0];
        v.y = s[dl * 33 + n4 + 1];
        v.z = s[dl * 33 + n4 + 2];
        v.w = s[dl * 33 + n4 + 3];
        *reinterpret_cast<float4*>(&dst[(bh * DINc + d0 + dl) * NPGc + n0 + n4]) = v;
    }
}

// ---------------- tf32 MMA GEMM: C[M,N] = scale*(A[M,K]@B[N,K]^T + bias[N]) ----------
// 128x128 block tile, 8 warps (2m x 4n), warp tile 64x32, K-chunk 32.
__global__ void __launch_bounds__(256)
k_gemm(const float* __restrict__ A, const float* __restrict__ B,
       const float* __restrict__ bias, float* __restrict__ C,
       int M, int N, int K, float scale) {
    __shared__ __align__(16) float sA[128 * 36];
    __shared__ __align__(16) float sB[128 * 36];
    int t  = threadIdx.x;
    int bm = blockIdx.y * 128;
    int bn = blockIdx.x * 128;
    int wid = t >> 5, lane = t & 31, gid = lane >> 2, tig = lane & 3;
    int wm = (wid & 1) * 64, wn = (wid >> 1) * 32;

    float c[4][4][4];
    #pragma unroll
    for (int i = 0; i < 4; i++)
        #pragma unroll
        for (int j = 0; j < 4; j++)
            #pragma unroll
            for (int r = 0; r < 4; r++) c[i][j][r] = 0.f;

    for (int kc = 0; kc < K; kc += 32) {
        #pragma unroll
        for (int l = 0; l < 4; l++) {
            int id = t + 256 * l;
            int row = id >> 3;
            int c4  = (id & 7) * 4;
            float4 v = *reinterpret_cast<const float4*>(&A[(bm + row) * K + kc + c4]);
            sA[row * 36 + c4 + 0] = tf32r(v.x);
            sA[row * 36 + c4 + 1] = tf32r(v.y);
            sA[row * 36 + c4 + 2] = tf32r(v.z);
            sA[row * 36 + c4 + 3] = tf32r(v.w);
            float4 w = *reinterpret_cast<const float4*>(&B[(bn + row) * K + kc + c4]);
            sB[row * 36 + c4 + 0] = tf32r(w.x);
            sB[row * 36 + c4 + 1] = tf32r(w.y);
            sB[row * 36 + c4 + 2] = tf32r(w.z);
            sB[row * 36 + c4 + 3] = tf32r(w.w);
        }
        __syncthreads();
        #pragma unroll
        for (int ks = 0; ks < 4; ks++) {
            int k0 = ks * 8;
            unsigned a[4][4], b[4][2];
            #pragma unroll
            for (int mt = 0; mt < 4; mt++) {
                int m = wm + 16 * mt + gid;
                a[mt][0] = fbits(sA[m * 36 + k0 + tig]);
                a[mt][1] = fbits(sA[(m + 8) * 36 + k0 + tig]);
                a[mt][2] = fbits(sA[m * 36 + k0 + tig + 4]);
                a[mt][3] = fbits(sA[(m + 8) * 36 + k0 + tig + 4]);
            }
            #pragma unroll
            for (int nt = 0; nt < 4; nt++) {
                int n = wn + 8 * nt + gid;
                b[nt][0] = fbits(sB[n * 36 + k0 + tig]);
                b[nt][1] = fbits(sB[n * 36 + k0 + tig + 4]);
            }
            #pragma unroll
            for (int mt = 0; mt < 4; mt++)
                #pragma unroll
                for (int nt = 0; nt < 4; nt++) mma8(c[mt][nt], a[mt], b[nt]);
        }
        __syncthreads();
    }

    #pragma unroll
    for (int mt = 0; mt < 4; mt++) {
        int r0 = bm + wm + 16 * mt + gid;
        #pragma unroll
        for (int nt = 0; nt < 4; nt++) {
            int col = bn + wn + 8 * nt + 2 * tig;
            float2 bb = *reinterpret_cast<const float2*>(&bias[col]);
            float2 o0, o1;
            o0.x = scale * (c[mt][nt][0] + bb.x);
            o0.y = scale * (c[mt][nt][1] + bb.y);
            o1.x = scale * (c[mt][nt][2] + bb.x);
            o1.y = scale * (c[mt][nt][3] + bb.y);
            *reinterpret_cast<float2*>(&C[r0 * N + col])       = o0;
            *reinterpret_cast<float2*>(&C[(r0 + 8) * N + col]) = o1;
        }
    }
}

// ---------------- L2-normalize rows of 128 (one warp per (n,h)) ----------------
__global__ void k_norm(float* __restrict__ buf) {
    int gt   = blockIdx.x * blockDim.x + threadIdx.x;
    int w    = gt >> 5;                 // warp over NN*HH rows
    int lane = threadIdx.x & 31;
    float4 v = reinterpret_cast<float4*>(buf)[w * 32 + lane];
    float ss = v.x * v.x + v.y * v.y + v.z * v.z + v.w * v.w;
    #pragma unroll
    for (int off = 16; off > 0; off >>= 1) ss += __shfl_xor_sync(0xffffffffu, ss, off);
    float r = 1.0f / sqrtf(ss);
    v.x *= r; v.y *= r; v.z *= r; v.w *= r;
    reinterpret_cast<float4*>(buf)[w * 32 + lane] = v;
}

// ---------------- column sums over nodes per (b,h): which==0 -> ksum from g_k, 1 -> vsum from g_cur
__global__ void k_colsum(int which) {
    int bh = blockIdx.x;
    int b = bh >> 2, h = bh & 3;
    int nb = blockIdx.y * 128;
    int e = threadIdx.x;
    const float* src = which ? g_cur : g_k;
    float* dst       = which ? g_vsum : g_ksum;
    float s = 0.f;
    for (int n = 0; n < 128; n++)
        s += src[((b * NPGc + nb + n) * HHc + h) * DINc + e];
    atomicAdd(&dst[bh * DINc + e], s);
}

// ---------------- den[n,h] = q . ksum + n_nodes (iteration-invariant) ----------------
__global__ void k_den(const int* __restrict__ n_nodes) {
    int gt   = blockIdx.x * blockDim.x + threadIdx.x;
    int w    = gt >> 5;                 // (n,h) index
    int lane = threadIdx.x & 31;
    int n = w >> 2, h = w & 3;
    int b = n >> 12;                    // NPG = 4096
    float4 q = reinterpret_cast<float4*>(g_q)[w * 32 + lane];
    float4 s = reinterpret_cast<float4*>(g_ksum)[((b << 2) | h) * 32 + lane];
    float d = q.x * s.x + q.y * s.y + q.z * s.z + q.w * s.w;
    #pragma unroll
    for (int off = 16; off > 0; off >>= 1) d += __shfl_xor_sync(0xffffffffu, d, off);
    if (lane == 0) g_den[w] = d + (float)n_nodes[b];
}

__global__ void k_zero_vsum() {
    int i = blockIdx.x * blockDim.x + threadIdx.x;
    if (i < BHc * DINc) g_vsum[i] = 0.f;
}

// ---------------- kv partials: kvp[sp][bh] = sum_{n in split} kT[:,n] x curT[:,n]^T ----
__global__ void __launch_bounds__(256) k_kv() {
    __shared__ __align__(16) float sK[128 * 36];
    __shared__ __align__(16) float sV[128 * 36];
    int bh = blockIdx.x, sp = blockIdx.y;
    int t = threadIdx.x;
    int wid = t >> 5, lane = t & 31, gid = lane >> 2, tig = lane & 3;
    int wm = (wid & 1) * 64, wn = (wid >> 1) * 32;
    const float* Kt = &g_kT  [bh * DINc * NPGc];
    const float* Vt = &g_curT[bh * DINc * NPGc];

    float c[4][4][4];
    #pragma unroll
    for (int i = 0; i < 4; i++)
        #pragma unroll
        for (int j = 0; j < 4; j++)
            #pragma unroll
            for (int r = 0; r < 4; r++) c[i][j][r] = 0.f;

    int nend = sp * 512 + 512;
    for (int nb = sp * 512; nb < nend; nb += 32) {
        #pragma unroll
        for (int l = 0; l < 4; l++) {
            int id = t + 256 * l;
            int row = id >> 3;
            int c4  = (id & 7) * 4;
            float4 v = *reinterpret_cast<const float4*>(&Kt[row * NPGc + nb + c4]);
            sK[row * 36 + c4 + 0] = tf32r(v.x);
            sK[row * 36 + c4 + 1] = tf32r(v.y);
            sK[row * 36 + c4 + 2] = tf32r(v.z);
            sK[row * 36 + c4 + 3] = tf32r(v.w);
            float4 w = *reinterpret_cast<const float4*>(&Vt[row * NPGc + nb + c4]);
            sV[row * 36 + c4 + 0] = tf32r(w.x);
            sV[row * 36 + c4 + 1] = tf32r(w.y);
            sV[row * 36 + c4 + 2] = tf32r(w.z);
            sV[row * 36 + c4 + 3] = tf32r(w.w);
        }
        __syncthreads();
        #pragma unroll
        for (int ks = 0; ks < 4; ks++) {
            int k0 = ks * 8;
            unsigned a[4][4], b[4][2];
            #pragma unroll
            for (int mt = 0; mt < 4; mt++) {
                int m = wm + 16 * mt + gid;
                a[mt][0] = fbits(sK[m * 36 + k0 + tig]);
                a[mt][1] = fbits(sK[(m + 8) * 36 + k0 + tig]);
                a[mt][2] = fbits(sK[m * 36 + k0 + tig + 4]);
                a[mt][3] = fbits(sK[(m + 8) * 36 + k0 + tig + 4]);
            }
            #pragma unroll
            for (int nt = 0; nt < 4; nt++) {
                int n = wn + 8 * nt + gid;
                b[nt][0] = fbits(sV[n * 36 + k0 + tig]);
                b[nt][1] = fbits(sV[n * 36 + k0 + tig + 4]);
            }
            #pragma unroll
            for (int mt = 0; mt < 4; mt++)
                #pragma unroll
                for (int nt = 0; nt < 4; nt++) mma8(c[mt][nt], a[mt], b[nt]);
        }
        __syncthreads();
    }

    float* dst = &g_kvp[(sp * BHc + bh) * (DINc * DINc)];
    #pragma unroll
    for (int mt = 0; mt < 4; mt++) {
        int r0 = wm + 16 * mt + gid;
        #pragma unroll
        for (int nt = 0; nt < 4; nt++) {
            int col = wn + 8 * nt + 2 * tig;
            *reinterpret_cast<float2*>(&dst[r0 * 128 + col]) =
                make_float2(c[mt][nt][0], c[mt][nt][1]);
            *reinterpret_cast<float2*>(&dst[(r0 + 8) * 128 + col]) =
                make_float2(c[mt][nt][2], c[mt][nt][3]);
        }
    }
}

__global__ void k_kvreduce() {
    int i = blockIdx.x * 256 + threadIdx.x;   // < 32*128*128 = 524288
    float s = 0.f;
    #pragma unroll
    for (int sp = 0; sp < 8; sp++) s += g_kvp[sp * (BHc * DINc * DINc) + i];
    g_kv[i] = s;
}

// ---------------- GCN gather: gcn[n] = sum_{e in CSR row n} w[e] * cur[col[e]] ----------------
__global__ void k_gcn() {
    int n = blockIdx.x;
    int t = threadIdx.x;             // 0..127, one float4 of the 512-wide feature
    int s = g_rowptr[n];
    int e = s + g_deg[n];
    float4 acc = make_float4(0.f, 0.f, 0.f, 0.f);
    for (int i = s; i < e; i++) {
        int   c = g_ecol[i];
        float w = g_ew[i];
        float4 v = reinterpret_cast<const float4*>(g_cur)[c * 128 + t];
        acc.x += w * v.x; acc.y += w * v.y; acc.z += w * v.z; acc.w += w * v.w;
    }
    reinterpret_cast<float4*>(g_gcn)[n * 128 + t] = acc;
}

// ---------------- combine: attn = (q@kv + vsum)/den; cur = .5*gcn + .5*attn; acc += cur
// Block tile: 128 nodes x 128 e, K = d = 128 in chunks of 32. tf32 MMA.
__global__ void __launch_bounds__(256) k_combine() {
    __shared__ __align__(16) float sQ [128 * 36];   // [node][d]
    __shared__ __align__(16) float sKV[32 * 136];   // [d][e]
    int bh = blockIdx.x, ch = blockIdx.y;
    int b = bh >> 2, h = bh & 3;
    int t = threadIdx.x;
    int wid = t >> 5, lane = t & 31, gid = lane >> 2, tig = lane & 3;
    int wm = (wid & 1) * 64, wn = (wid >> 1) * 32;
    int nbase = ch * 128;

    float c[4][4][4];
    #pragma unroll
    for (int i = 0; i < 4; i++)
        #pragma unroll
        for (int j = 0; j < 4; j++)
            #pragma unroll
            for (int r = 0; r < 4; r++) c[i][j][r] = 0.f;

    for (int kc = 0; kc < 128; kc += 32) {
        #pragma unroll
        for (int l = 0; l < 4; l++) {
            int id = t + 256 * l;
            int row = id >> 3;
            int c4  = (id & 7) * 4;
            float4 v = *reinterpret_cast<const float4*>(
                &g_q[((b * NPGc + nbase + row) * HHc + h) * DINc + kc + c4]);
            sQ[row * 36 + c4 + 0] = tf32r(v.x);
            sQ[row * 36 + c4 + 1] = tf32r(v.y);
            sQ[row * 36 + c4 + 2] = tf32r(v.z);
            sQ[row * 36 + c4 + 3] = tf32r(v.w);
            int drow = id >> 5;          // 0..31
            int e4   = (id & 31) * 4;
            float4 w = *reinterpret_cast<const float4*>(
                &g_kv[bh * (DINc * DINc) + (kc + drow) * 128 + e4]);
            sKV[drow * 136 + e4 + 0] = tf32r(w.x);
            sKV[drow * 136 + e4 + 1] = tf32r(w.y);
            sKV[drow * 136 + e4 + 2] = tf32r(w.z);
            sKV[drow * 136 + e4 + 3] = tf32r(w.w);
        }
        __syncthreads();
        #pragma unroll
        for (int ks = 0; ks < 4; ks++) {
            int k0 = ks * 8;
            unsigned a[4][4], bfr[4][2];
            #pragma unroll
            for (int mt = 0; mt < 4; mt++) {
                int m = wm + 16 * mt + gid;
                a[mt][0] = fbits(sQ[m * 36 + k0 + tig]);
                a[mt][1] = fbits(sQ[(m + 8) * 36 + k0 + tig]);
                a[mt][2] = fbits(sQ[m * 36 + k0 + tig + 4]);
                a[mt][3] = fbits(sQ[(m + 8) * 36 + k0 + tig + 4]);
            }
            #pragma unroll
            for (int nt = 0; nt < 4; nt++) {
                int e = wn + 8 * nt + gid;
                bfr[nt][0] = fbits(sKV[(k0 + tig) * 136 + e]);
                bfr[nt][1] = fbits(sKV[(k0 + tig + 4) * 136 + e]);
            }
            #pragma unroll
            for (int mt = 0; mt < 4; mt++)
                #pragma unroll
                for (int nt = 0; nt < 4; nt++) mma8(c[mt][nt], a[mt], bfr[nt]);
        }
        __syncthreads();
    }

    #pragma unroll
    for (int mt = 0; mt < 4; mt++) {
        int nl0 = nbase + wm + 16 * mt + gid;
        #pragma unroll
        for (int half = 0; half < 2; half++) {
            int nl = nl0 + half * 8;
            float inv = 1.0f / g_den[(b * NPGc + nl) * HHc + h];
            #pragma unroll
            for (int nt = 0; nt < 4; nt++) {
                int e = wn + 8 * nt + 2 * tig;
                int base = ((b * NPGc + nl) * HHc + h) * DINc + e;
                float cv0 = c[mt][nt][half * 2 + 0];
                float cv1 = c[mt][nt][half * 2 + 1];
                float2 vs = *reinterpret_cast<const float2*>(&g_vsum[bh * DINc + e]);
                float2 gc = *reinterpret_cast<const float2*>(&g_gcn[base]);
                float2 ac = *reinterpret_cast<const float2*>(&g_acc[base]);
                float o0 = 0.5f * (gc.x + (cv0 + vs.x) * inv);
                float o1 = 0.5f * (gc.y + (cv1 + vs.y) * inv);
                *reinterpret_cast<float2*>(&g_cur[base]) = make_float2(o0, o1);
                *reinterpret_cast<float2*>(&g_acc[base]) = make_float2(ac.x + o0, ac.y + o1);
            }
        }
    }
}

// ---------------- launcher ----------------
extern "C" void kernel_launch(void* const* d_in, const int* in_sizes, int n_in,
                              void* d_out, int out_size) {
    const float* x    = (const float*)d_in[0];
    const float* Wq_w = (const float*)d_in[1];
    const float* Wq_b = (const float*)d_in[2];
    const float* Wk_w = (const float*)d_in[3];
    const float* Wk_b = (const float*)d_in[4];
    const float* Wo_w = (const float*)d_in[5];
    const float* Wo_b = (const float*)d_in[6];
    const int*   edge = (const int*)d_in[7];
    const int*   nnod = (const int*)d_in[8];
    const int* row = edge;
    const int* col = edge + EEc;
    float* out = (float*)d_out;

    float *pq, *pk, *pacc, *pcur, *pkT, *pcurT;
    cudaGetSymbolAddress((void**)&pq,    g_q);
    cudaGetSymbolAddress((void**)&pk,    g_k);
    cudaGetSymbolAddress((void**)&pacc,  g_acc);
    cudaGetSymbolAddress((void**)&pcur,  g_cur);
    cudaGetSymbolAddress((void**)&pkT,   g_kT);
    cudaGetSymbolAddress((void**)&pcurT, g_curT);

    // init + graph preprocessing (once per call)
    k_init<<<16384, 256>>>(x);
    k_zero_pre<<<128, 256>>>();
    k_count<<<1024, 256>>>(row);
    k_dis<<<128, 256>>>();
    k_scanA<<<128, 256>>>();
    k_scanB<<<1, 128>>>();
    k_scanC<<<128, 256>>>();
    k_fill<<<1024, 256>>>(row, col);

    // projections + normalization + invariant attention terms
    k_gemm<<<dim3(4, 256), 256>>>(x, Wq_w, Wq_b, pq, NN, CDIM, DINc, 1.0f);
    k_gemm<<<dim3(4, 256), 256>>>(x, Wk_w, Wk_b, pk, NN, CDIM, DINc, 1.0f);
    k_norm<<<16384, 256>>>(pq);
    k_norm<<<16384, 256>>>(pk);
    k_colsum<<<dim3(32, 32), 128>>>(0);            // ksum
    k_den<<<16384, 256>>>(nnod);
    k_transpose<<<dim3(32, 128, 4), 256>>>(pk, pkT);   // kT once (k invariant)

    // K_ORDER = 4 propagation steps
    for (int it = 0; it < 4; it++) {
        k_zero_vsum<<<16, 256>>>();
        k_colsum<<<dim3(32, 32), 128>>>(1);            // vsum from cur
        k_transpose<<<dim3(32, 128, 4), 256>>>(pcur, pcurT);
        k_kv<<<dim3(32, 8), 256>>>();
        k_kvreduce<<<2048, 256>>>();
        k_gcn<<<32768, 128>>>();
        k_combine<<<dim3(32, 32), 256>>>();
    }

    // out = (acc @ Wo^T + b) / H
    k_gemm<<<dim3(1, 256), 256>>>(pacc, Wo_w, Wo_b, out, NN, DINc, CDIM, 0.25f);
}